// round 9
// baseline (speedup 1.0000x reference)
#include <cuda_runtime.h>

#define Bn   16
#define CIN  64
#define COUT 64
#define Hn   130
#define Wn   130
#define HOn  128
#define WOn  128
#define Gn   8
#define CPGn 8
#define OFFC 144   // G*2*K*K
#define HWo  16384 // 128*128
#define HWi  16900 // 130*130

// Intermediate feature map t = conv3x3(x, w1) + b1  : [16,64,128,128]
__device__ float g_t[(size_t)Bn * CIN * HOn * WOn];

// ---- packed fp32x2 helpers (Blackwell FFMA2, PTX-only) ---------------------
__device__ __forceinline__ unsigned long long pack2(float v) {
    unsigned long long r;
    asm("mov.b64 %0, {%1, %1};" : "=l"(r) : "f"(v));
    return r;
}
__device__ __forceinline__ void ffma2(unsigned long long& a,
                                      unsigned long long w,
                                      unsigned long long v) {
    asm("fma.rn.f32x2 %0, %1, %2, %0;" : "+l"(a) : "l"(w), "l"(v));
}
__device__ __forceinline__ void unpack2(unsigned long long a, float& lo, float& hi) {
    asm("mov.b64 {%0, %1}, %2;" : "=f"(lo), "=f"(hi) : "l"(a));
}

// ---------------------------------------------------------------------------
// Kernel 1: 3x3 VALID conv, 64->64. Reg-neutral FFMA2.
// Tile 32x16 spatial x 16 out-ch per block; thread = 2 y-pixels x 16 co
// (8 packed u64 acc per row = same 32 acc regs as scalar).
// 2 input channels staged per barrier.
// ---------------------------------------------------------------------------
__global__ __launch_bounds__(256, 4) void conv3x3_kernel(
    const float* __restrict__ x, const float* __restrict__ w1,
    const float* __restrict__ b1)
{
    const int tx = threadIdx.x;            // 0..31
    const int ty = threadIdx.y;            // 0..7
    const int tid = ty * 32 + tx;
    const int tileX = blockIdx.x * 32;
    const int tileY = blockIdx.y * 16;
    const int b = blockIdx.z >> 2;
    const int coBase = (blockIdx.z & 3) * 16;

    __shared__ float s_in[2][18][36];                 // 2 ci x (16+2) x (32+2)
    __shared__ __align__(16) float s_w[2][9][16];     // [ci2][tap][co]

    unsigned long long acc0[8], acc1[8];              // 16 co per row, packed
#pragma unroll
    for (int i = 0; i < 8; ++i) { acc0[i] = 0ull; acc1[i] = 0ull; }

    for (int ci0 = 0; ci0 < CIN; ci0 += 2) {
#pragma unroll
        for (int cc = 0; cc < 2; ++cc) {
            const float* xp = x + ((size_t)(b * CIN + ci0 + cc)) * HWi;
            for (int e = tid; e < 18 * 34; e += 256) {
                int r = e / 34, c = e - r * 34;
                s_in[cc][r][c] = xp[(tileY + r) * Wn + (tileX + c)];
            }
        }
        for (int e = tid; e < 288; e += 256) {
            int cc = e / 144;
            int k  = (e % 144) >> 4;
            int co = e & 15;
            s_w[cc][k][co] = w1[((size_t)(coBase + co) * CIN + ci0 + cc) * 9 + k];
        }
        __syncthreads();

#pragma unroll
        for (int cc = 0; cc < 2; ++cc) {
            float in[4][3];
#pragma unroll
            for (int r = 0; r < 4; ++r)
#pragma unroll
                for (int c = 0; c < 3; ++c)
                    in[r][c] = s_in[cc][ty * 2 + r][tx + c];

#pragma unroll
            for (int ky = 0; ky < 3; ++ky)
#pragma unroll
                for (int kx = 0; kx < 3; ++kx) {
                    unsigned long long i0 = pack2(in[ky][kx]);
                    unsigned long long i1 = pack2(in[ky + 1][kx]);
                    const ulonglong2* wp = (const ulonglong2*)s_w[cc][ky * 3 + kx];
#pragma unroll
                    for (int q = 0; q < 4; ++q) {
                        ulonglong2 w = wp[q];
                        ffma2(acc0[q * 2 + 0], w.x, i0);
                        ffma2(acc0[q * 2 + 1], w.y, i0);
                        ffma2(acc1[q * 2 + 0], w.x, i1);
                        ffma2(acc1[q * 2 + 1], w.y, i1);
                    }
                }
        }
        __syncthreads();
    }

    const int oy = tileY + ty * 2;
    const int ox = tileX + tx;
#pragma unroll
    for (int q = 0; q < 8; ++q) {
        float a0lo, a0hi, a1lo, a1hi;
        unpack2(acc0[q], a0lo, a0hi);
        unpack2(acc1[q], a1lo, a1hi);
        int co = coBase + q * 2;
        float bb0 = b1[co], bb1 = b1[co + 1];
        size_t base0 = ((size_t)(b * COUT + co)) * HWo;
        size_t base1 = base0 + HWo;
        g_t[base0 + (size_t)oy * WOn + ox]       = a0lo + bb0;
        g_t[base0 + (size_t)(oy + 1) * WOn + ox] = a1lo + bb0;
        g_t[base1 + (size_t)oy * WOn + ox]       = a0hi + bb1;
        g_t[base1 + (size_t)(oy + 1) * WOn + ox] = a1hi + bb1;
    }
}

// ---------------------------------------------------------------------------
// Kernel 2: 1x1 conv 64->144 (offset prediction), FFMA2 packed (reg-neutral).
// Block: 256 pixels x 48 out-ch, thread = 1 pixel, 24 packed acc.
// ---------------------------------------------------------------------------
__global__ __launch_bounds__(256, 2) void conv1x1_kernel(
    const float* __restrict__ w2, const float* __restrict__ b2,
    float* __restrict__ off)
{
    __shared__ __align__(16) float s_w[64 * 48];   // [cin][co48]
    __shared__ float s_t[16][256];

    const int tid = threadIdx.x;
    const int coBase = blockIdx.y * 48;
    const int p0 = blockIdx.x * 256;
    const int b = p0 >> 14;
    const int hwBase = p0 & (HWo - 1);

    for (int e = tid; e < 64 * 48; e += 256) {
        int cin = e / 48, co = e - cin * 48;
        s_w[e] = w2[(size_t)(coBase + co) * CIN + cin];
    }

    unsigned long long acc[24];
#pragma unroll
    for (int i = 0; i < 24; ++i) acc[i] = 0ull;

    for (int chunk = 0; chunk < 4; ++chunk) {
        __syncthreads();
#pragma unroll
        for (int r = 0; r < 16; ++r)
            s_t[r][tid] = g_t[((size_t)(b * CIN + chunk * 16 + r)) * HWo + hwBase + tid];
        __syncthreads();
#pragma unroll
        for (int r = 0; r < 16; ++r) {
            unsigned long long tv = pack2(s_t[r][tid]);
            const ulonglong2* wp = (const ulonglong2*)(s_w + (chunk * 16 + r) * 48);
#pragma unroll
            for (int q = 0; q < 12; ++q) {
                ulonglong2 w = wp[q];
                ffma2(acc[q * 2 + 0], w.x, tv);
                ffma2(acc[q * 2 + 1], w.y, tv);
            }
        }
    }

    const int hw = hwBase + tid;
#pragma unroll
    for (int q = 0; q < 24; ++q) {
        float lo, hi;
        unpack2(acc[q], lo, hi);
        int co = coBase + q * 2;
        off[((size_t)(b * OFFC + co)) * HWo + hw]     = lo + b2[co];
        off[((size_t)(b * OFFC + co + 1)) * HWo + hw] = hi + b2[co + 1];
    }
}

// ---------------------------------------------------------------------------
// Kernel 3: deformable conv, co-split for occupancy.
// Thread = 1 output pixel x 32 out channels (16 packed u64 acc = 32 regs).
// blockIdx.z = b*2 + coHalf. Target 4 blocks/SM (32 warps) for latency hiding.
// ---------------------------------------------------------------------------
__global__ __launch_bounds__(256, 4) void deform_kernel(
    const float* __restrict__ x, const float* __restrict__ wd,
    const float* __restrict__ off, float* __restrict__ y)
{
    __shared__ __align__(16) float s_wd[9 * 8 * 32];   // [ij][c][co32]

    const int tx = threadIdx.x;      // 0..31
    const int ty = threadIdx.y;      // 0..7
    const int tid = ty * 32 + tx;
    const int wo = blockIdx.x * 32 + tx;
    const int ho = blockIdx.y * 8 + ty;
    const int b = blockIdx.z >> 1;
    const int coBase = (blockIdx.z & 1) * 32;

    unsigned long long acc[16];
#pragma unroll
    for (int i = 0; i < 16; ++i) acc[i] = 0ull;

    for (int g = 0; g < Gn; ++g) {
        __syncthreads();   // previous group's compute done before overwrite
        for (int e = tid; e < 2304; e += 256) {
            int co = e & 31;
            int c  = (e >> 5) & 7;
            int ij = e >> 8;
            int i = ij / 3, j = ij - i * 3;
            s_wd[e] = wd[(((size_t)(coBase + co) * CIN + g * CPGn + c) * 3 + i) * 3 + j];
        }
        __syncthreads();

        const float* xg = x + ((size_t)(b * CIN + g * CPGn)) * HWi;

        for (int ij = 0; ij < 9; ++ij) {
            const int i = ij / 3, j = ij - i * 3;
            const size_t obase = ((size_t)(b * OFFC + (g * 9 + ij) * 2)) * HWo
                               + ho * WOn + wo;
            float dy = __ldg(off + obase);
            float dx = __ldg(off + obase + HWo);

            float py = dy + (float)(ho + i);
            float px = dx + (float)(wo + j);
            float y0f = floorf(py), x0f = floorf(px);
            float ly = py - y0f, lx = px - x0f;
            int y0 = (int)y0f, x0 = (int)x0f;
            int y1 = y0 + 1, x1 = x0 + 1;

            float vy0 = (y0 >= 0 && y0 < Hn) ? 1.f : 0.f;
            float vy1 = (y1 >= 0 && y1 < Hn) ? 1.f : 0.f;
            float vx0 = (x0 >= 0 && x0 < Wn) ? 1.f : 0.f;
            float vx1 = (x1 >= 0 && x1 < Wn) ? 1.f : 0.f;

            float w00 = (1.f - ly) * (1.f - lx) * vy0 * vx0;
            float w01 = (1.f - ly) * lx * vy0 * vx1;
            float w10 = ly * (1.f - lx) * vy1 * vx0;
            float w11 = ly * lx * vy1 * vx1;

            int yc0 = min(max(y0, 0), Hn - 1), yc1 = min(max(y1, 0), Hn - 1);
            int xc0 = min(max(x0, 0), Wn - 1), xc1 = min(max(x1, 0), Wn - 1);
            int i00 = yc0 * Wn + xc0, i01 = yc0 * Wn + xc1;
            int i10 = yc1 * Wn + xc0, i11 = yc1 * Wn + xc1;

#pragma unroll
            for (int c = 0; c < 8; ++c) {
                const float* p = xg + (size_t)c * HWi;
                float v = w00 * __ldg(p + i00) + w01 * __ldg(p + i01)
                        + w10 * __ldg(p + i10) + w11 * __ldg(p + i11);
                unsigned long long vp = pack2(v);
                const ulonglong2* wrow = (const ulonglong2*)(s_wd + (ij * 8 + c) * 32);
#pragma unroll
                for (int q = 0; q < 8; ++q) {
                    ulonglong2 w = wrow[q];
                    ffma2(acc[q * 2 + 0], w.x, vp);
                    ffma2(acc[q * 2 + 1], w.y, vp);
                }
            }
        }
    }

#pragma unroll
    for (int q = 0; q < 16; ++q) {
        float lo, hi;
        unpack2(acc[q], lo, hi);
        size_t base = ((size_t)(b * COUT + coBase + q * 2)) * HWo + ho * WOn + wo;
        y[base]       = lo;
        y[base + HWo] = hi;
    }
}

// ---------------------------------------------------------------------------
extern "C" void kernel_launch(void* const* d_in, const int* in_sizes, int n_in,
                              void* d_out, int out_size)
{
    const float* x  = (const float*)d_in[0];
    const float* w1 = (const float*)d_in[1];
    const float* b1 = (const float*)d_in[2];
    const float* w2 = (const float*)d_in[3];
    const float* b2 = (const float*)d_in[4];
    const float* wd = (const float*)d_in[5];

    float* y   = (float*)d_out;
    float* off = y + (size_t)Bn * COUT * HOn * WOn;   // off is output #2

    conv3x3_kernel<<<dim3(4, 8, Bn * 4), dim3(32, 8)>>>(x, w1, b1);
    conv1x1_kernel<<<dim3((Bn * HWo) / 256, 3), 256>>>(w2, b2, off);
    deform_kernel<<<dim3(WOn / 32, HOn / 8, Bn * 2), dim3(32, 8)>>>(x, wd, off, y);
}

// round 10
// speedup vs baseline: 1.0289x; 1.0289x over previous
#include <cuda_runtime.h>

#define Bn   16
#define CIN  64
#define COUT 64
#define Hn   130
#define Wn   130
#define HOn  128
#define WOn  128
#define Gn   8
#define CPGn 8
#define OFFC 144   // G*2*K*K
#define HWo  16384 // 128*128
#define HWi  16900 // 130*130

// Intermediate feature map t = conv3x3(x, w1) + b1  : [16,64,128,128]
__device__ float g_t[(size_t)Bn * CIN * HOn * WOn];
// Transposed input: xt[b][g][y][x][c8] (grouped NHWC8)
__device__ float g_xt[(size_t)Bn * Gn * HWi * CPGn];

// ---- packed fp32x2 helpers (Blackwell FFMA2, PTX-only) ---------------------
__device__ __forceinline__ unsigned long long pack2(float v) {
    unsigned long long r;
    asm("mov.b64 %0, {%1, %1};" : "=l"(r) : "f"(v));
    return r;
}
__device__ __forceinline__ void ffma2(unsigned long long& a,
                                      unsigned long long w,
                                      unsigned long long v) {
    asm("fma.rn.f32x2 %0, %1, %2, %0;" : "+l"(a) : "l"(w), "l"(v));
}
__device__ __forceinline__ void unpack2(unsigned long long a, float& lo, float& hi) {
    asm("mov.b64 {%0, %1}, %2;" : "=f"(lo), "=f"(hi) : "l"(a));
}

// ---------------------------------------------------------------------------
// Kernel 0: transpose x [b, g*8+c, y, x] -> xt [b, g, y, x, c8].
// One block per (y, g, b) row; smem-staged so both sides are coalesced.
// ---------------------------------------------------------------------------
__global__ __launch_bounds__(256) void transpose_kernel(const float* __restrict__ x)
{
    __shared__ float s[8][132];
    const int yy = blockIdx.x;
    const int g  = blockIdx.y;
    const int b  = blockIdx.z;
    const int tid = threadIdx.x;

    const size_t rbase = ((size_t)(b * CIN + g * CPGn)) * HWi + (size_t)yy * Wn;
    for (int e = tid; e < 8 * Wn; e += 256) {
        int c = e / Wn, xx = e - c * Wn;
        s[c][xx] = x[rbase + (size_t)c * HWi + xx];
    }
    __syncthreads();

    const size_t wbase = (((size_t)(b * Gn + g)) * HWi + (size_t)yy * Wn) * CPGn;
    for (int e = tid; e < 8 * Wn; e += 256) {
        int xx = e >> 3, c = e & 7;
        g_xt[wbase + e] = s[c][xx];
    }
}

// ---------------------------------------------------------------------------
// Kernel 1: 3x3 VALID conv, 64->64. Reg-neutral FFMA2 (round-9, 516us).
// ---------------------------------------------------------------------------
__global__ __launch_bounds__(256, 4) void conv3x3_kernel(
    const float* __restrict__ x, const float* __restrict__ w1,
    const float* __restrict__ b1)
{
    const int tx = threadIdx.x;            // 0..31
    const int ty = threadIdx.y;            // 0..7
    const int tid = ty * 32 + tx;
    const int tileX = blockIdx.x * 32;
    const int tileY = blockIdx.y * 16;
    const int b = blockIdx.z >> 2;
    const int coBase = (blockIdx.z & 3) * 16;

    __shared__ float s_in[2][18][36];
    __shared__ __align__(16) float s_w[2][9][16];

    unsigned long long acc0[8], acc1[8];
#pragma unroll
    for (int i = 0; i < 8; ++i) { acc0[i] = 0ull; acc1[i] = 0ull; }

    for (int ci0 = 0; ci0 < CIN; ci0 += 2) {
#pragma unroll
        for (int cc = 0; cc < 2; ++cc) {
            const float* xp = x + ((size_t)(b * CIN + ci0 + cc)) * HWi;
            for (int e = tid; e < 18 * 34; e += 256) {
                int r = e / 34, c = e - r * 34;
                s_in[cc][r][c] = xp[(tileY + r) * Wn + (tileX + c)];
            }
        }
        for (int e = tid; e < 288; e += 256) {
            int cc = e / 144;
            int k  = (e % 144) >> 4;
            int co = e & 15;
            s_w[cc][k][co] = w1[((size_t)(coBase + co) * CIN + ci0 + cc) * 9 + k];
        }
        __syncthreads();

#pragma unroll
        for (int cc = 0; cc < 2; ++cc) {
            float in[4][3];
#pragma unroll
            for (int r = 0; r < 4; ++r)
#pragma unroll
                for (int c = 0; c < 3; ++c)
                    in[r][c] = s_in[cc][ty * 2 + r][tx + c];

#pragma unroll
            for (int ky = 0; ky < 3; ++ky)
#pragma unroll
                for (int kx = 0; kx < 3; ++kx) {
                    unsigned long long i0 = pack2(in[ky][kx]);
                    unsigned long long i1 = pack2(in[ky + 1][kx]);
                    const ulonglong2* wp = (const ulonglong2*)s_w[cc][ky * 3 + kx];
#pragma unroll
                    for (int q = 0; q < 4; ++q) {
                        ulonglong2 w = wp[q];
                        ffma2(acc0[q * 2 + 0], w.x, i0);
                        ffma2(acc0[q * 2 + 1], w.y, i0);
                        ffma2(acc1[q * 2 + 0], w.x, i1);
                        ffma2(acc1[q * 2 + 1], w.y, i1);
                    }
                }
        }
        __syncthreads();
    }

    const int oy = tileY + ty * 2;
    const int ox = tileX + tx;
#pragma unroll
    for (int q = 0; q < 8; ++q) {
        float a0lo, a0hi, a1lo, a1hi;
        unpack2(acc0[q], a0lo, a0hi);
        unpack2(acc1[q], a1lo, a1hi);
        int co = coBase + q * 2;
        float bb0 = b1[co], bb1 = b1[co + 1];
        size_t base0 = ((size_t)(b * COUT + co)) * HWo;
        size_t base1 = base0 + HWo;
        g_t[base0 + (size_t)oy * WOn + ox]       = a0lo + bb0;
        g_t[base0 + (size_t)(oy + 1) * WOn + ox] = a1lo + bb0;
        g_t[base1 + (size_t)oy * WOn + ox]       = a0hi + bb1;
        g_t[base1 + (size_t)(oy + 1) * WOn + ox] = a1hi + bb1;
    }
}

// ---------------------------------------------------------------------------
// Kernel 2: 1x1 conv 64->144 (offset prediction), FFMA2 packed (reg-neutral).
// ---------------------------------------------------------------------------
__global__ __launch_bounds__(256, 2) void conv1x1_kernel(
    const float* __restrict__ w2, const float* __restrict__ b2,
    float* __restrict__ off)
{
    __shared__ __align__(16) float s_w[64 * 48];
    __shared__ float s_t[16][256];

    const int tid = threadIdx.x;
    const int coBase = blockIdx.y * 48;
    const int p0 = blockIdx.x * 256;
    const int b = p0 >> 14;
    const int hwBase = p0 & (HWo - 1);

    for (int e = tid; e < 64 * 48; e += 256) {
        int cin = e / 48, co = e - cin * 48;
        s_w[e] = w2[(size_t)(coBase + co) * CIN + cin];
    }

    unsigned long long acc[24];
#pragma unroll
    for (int i = 0; i < 24; ++i) acc[i] = 0ull;

    for (int chunk = 0; chunk < 4; ++chunk) {
        __syncthreads();
#pragma unroll
        for (int r = 0; r < 16; ++r)
            s_t[r][tid] = g_t[((size_t)(b * CIN + chunk * 16 + r)) * HWo + hwBase + tid];
        __syncthreads();
#pragma unroll
        for (int r = 0; r < 16; ++r) {
            unsigned long long tv = pack2(s_t[r][tid]);
            const ulonglong2* wp = (const ulonglong2*)(s_w + (chunk * 16 + r) * 48);
#pragma unroll
            for (int q = 0; q < 12; ++q) {
                ulonglong2 w = wp[q];
                ffma2(acc[q * 2 + 0], w.x, tv);
                ffma2(acc[q * 2 + 1], w.y, tv);
            }
        }
    }

    const int hw = hwBase + tid;
#pragma unroll
    for (int q = 0; q < 24; ++q) {
        float lo, hi;
        unpack2(acc[q], lo, hi);
        int co = coBase + q * 2;
        off[((size_t)(b * OFFC + co)) * HWo + hw]     = lo + b2[co];
        off[((size_t)(b * OFFC + co + 1)) * HWo + hw] = hi + b2[co + 1];
    }
}

// ---------------------------------------------------------------------------
// Kernel 3: deformable conv (round-3 structure: 64 co, scalar accumulate),
// but gathers from NHWC8 xt: each corner = 2x LDG.128 (8 ch contiguous)
// instead of 8 scalar LDGs. 4x fewer gather loads / scoreboard chains.
// ---------------------------------------------------------------------------
__global__ __launch_bounds__(256, 2) void deform_kernel(
    const float* __restrict__ wd, const float* __restrict__ off,
    float* __restrict__ y)
{
    __shared__ __align__(16) float s_wd[9 * 64 * 8];   // [ij][co][c]

    const int tx = threadIdx.x;      // 0..31
    const int ty = threadIdx.y;      // 0..7
    const int tid = ty * 32 + tx;
    const int wo = blockIdx.x * 32 + tx;
    const int ho = blockIdx.y * 8 + ty;
    const int b = blockIdx.z;

    float acc[64];
#pragma unroll
    for (int i = 0; i < 64; ++i) acc[i] = 0.f;

    for (int g = 0; g < Gn; ++g) {
        __syncthreads();   // previous group's compute done before overwrite
        for (int e = tid; e < 4608; e += 256) {
            int c = e & 7;
            int co = (e >> 3) & 63;
            int ij = e >> 9;
            int i = ij / 3, j = ij - i * 3;
            s_wd[e] = wd[(((size_t)co * CIN + g * CPGn + c) * 3 + i) * 3 + j];
        }
        __syncthreads();

        const float* xg = g_xt + ((size_t)(b * Gn + g)) * HWi * CPGn;

        for (int ij = 0; ij < 9; ++ij) {
            const int i = ij / 3, j = ij - i * 3;
            const size_t obase = ((size_t)(b * OFFC + (g * 9 + ij) * 2)) * HWo
                               + ho * WOn + wo;
            float dy = __ldg(off + obase);
            float dx = __ldg(off + obase + HWo);

            float py = dy + (float)(ho + i);
            float px = dx + (float)(wo + j);
            float y0f = floorf(py), x0f = floorf(px);
            float ly = py - y0f, lx = px - x0f;
            int y0 = (int)y0f, x0 = (int)x0f;
            int y1 = y0 + 1, x1 = x0 + 1;

            float vy0 = (y0 >= 0 && y0 < Hn) ? 1.f : 0.f;
            float vy1 = (y1 >= 0 && y1 < Hn) ? 1.f : 0.f;
            float vx0 = (x0 >= 0 && x0 < Wn) ? 1.f : 0.f;
            float vx1 = (x1 >= 0 && x1 < Wn) ? 1.f : 0.f;

            float w00 = (1.f - ly) * (1.f - lx) * vy0 * vx0;
            float w01 = (1.f - ly) * lx * vy0 * vx1;
            float w10 = ly * (1.f - lx) * vy1 * vx0;
            float w11 = ly * lx * vy1 * vx1;

            int yc0 = min(max(y0, 0), Hn - 1), yc1 = min(max(y1, 0), Hn - 1);
            int xc0 = min(max(x0, 0), Wn - 1), xc1 = min(max(x1, 0), Wn - 1);
            const float4* p00 = (const float4*)(xg + (size_t)(yc0 * Wn + xc0) * 8);
            const float4* p01 = (const float4*)(xg + (size_t)(yc0 * Wn + xc1) * 8);
            const float4* p10 = (const float4*)(xg + (size_t)(yc1 * Wn + xc0) * 8);
            const float4* p11 = (const float4*)(xg + (size_t)(yc1 * Wn + xc1) * 8);

            float4 a00 = __ldg(p00), b00 = __ldg(p00 + 1);
            float4 a01 = __ldg(p01), b01 = __ldg(p01 + 1);
            float4 a10 = __ldg(p10), b10 = __ldg(p10 + 1);
            float4 a11 = __ldg(p11), b11 = __ldg(p11 + 1);

            float v[8];
            v[0] = w00 * a00.x + w01 * a01.x + w10 * a10.x + w11 * a11.x;
            v[1] = w00 * a00.y + w01 * a01.y + w10 * a10.y + w11 * a11.y;
            v[2] = w00 * a00.z + w01 * a01.z + w10 * a10.z + w11 * a11.z;
            v[3] = w00 * a00.w + w01 * a01.w + w10 * a10.w + w11 * a11.w;
            v[4] = w00 * b00.x + w01 * b01.x + w10 * b10.x + w11 * b11.x;
            v[5] = w00 * b00.y + w01 * b01.y + w10 * b10.y + w11 * b11.y;
            v[6] = w00 * b00.z + w01 * b01.z + w10 * b10.z + w11 * b11.z;
            v[7] = w00 * b00.w + w01 * b01.w + w10 * b10.w + w11 * b11.w;

            const float4* wrow = (const float4*)(s_wd + ij * 512);
#pragma unroll
            for (int co = 0; co < 64; ++co) {
                float4 wa = wrow[co * 2];
                float4 wb = wrow[co * 2 + 1];
                acc[co] += v[0] * wa.x + v[1] * wa.y + v[2] * wa.z + v[3] * wa.w
                         + v[4] * wb.x + v[5] * wb.y + v[6] * wb.z + v[7] * wb.w;
            }
        }
    }

#pragma unroll
    for (int co = 0; co < 64; ++co)
        y[((size_t)(b * COUT + co)) * HWo + ho * WOn + wo] = acc[co];
}

// ---------------------------------------------------------------------------
extern "C" void kernel_launch(void* const* d_in, const int* in_sizes, int n_in,
                              void* d_out, int out_size)
{
    const float* x  = (const float*)d_in[0];
    const float* w1 = (const float*)d_in[1];
    const float* b1 = (const float*)d_in[2];
    const float* w2 = (const float*)d_in[3];
    const float* b2 = (const float*)d_in[4];
    const float* wd = (const float*)d_in[5];

    float* y   = (float*)d_out;
    float* off = y + (size_t)Bn * COUT * HOn * WOn;   // off is output #2

    transpose_kernel<<<dim3(Hn, Gn, Bn), 256>>>(x);
    conv3x3_kernel<<<dim3(4, 8, Bn * 4), dim3(32, 8)>>>(x, w1, b1);
    conv1x1_kernel<<<dim3((Bn * HWo) / 256, 3), 256>>>(w2, b2, off);
    deform_kernel<<<dim3(WOn / 32, HOn / 8, Bn), dim3(32, 8)>>>(wd, off, y);
}

// round 13
// speedup vs baseline: 1.1007x; 1.0698x over previous
#include <cuda_runtime.h>

#define Bn   16
#define CIN  64
#define COUT 64
#define Hn   130
#define Wn   130
#define HOn  128
#define WOn  128
#define Gn   8
#define CPGn 8
#define OFFC 144   // G*2*K*K
#define HWo  16384 // 128*128
#define HWi  16900 // 130*130

// Intermediate feature map t = conv3x3(x, w1) + b1  : [16,64,128,128]
__device__ float g_t[(size_t)Bn * CIN * HOn * WOn];
// Transposed input: xt[b][g][y][x][c8] (grouped NHWC8)
__device__ float g_xt[(size_t)Bn * Gn * HWi * CPGn];

// ---- packed fp32x2 helpers (Blackwell FFMA2, PTX-only) ---------------------
__device__ __forceinline__ unsigned long long pack2(float v) {
    unsigned long long r;
    asm("mov.b64 %0, {%1, %1};" : "=l"(r) : "f"(v));
    return r;
}
__device__ __forceinline__ void ffma2(unsigned long long& a,
                                      unsigned long long w,
                                      unsigned long long v) {
    asm("fma.rn.f32x2 %0, %1, %2, %0;" : "+l"(a) : "l"(w), "l"(v));
}
__device__ __forceinline__ void unpack2(unsigned long long a, float& lo, float& hi) {
    asm("mov.b64 {%0, %1}, %2;" : "=f"(lo), "=f"(hi) : "l"(a));
}

// ---------------------------------------------------------------------------
// Kernel 0: transpose x [b, g*8+c, y, x] -> xt [b, g, y, x, c8].
// ---------------------------------------------------------------------------
__global__ __launch_bounds__(256) void transpose_kernel(const float* __restrict__ x)
{
    __shared__ float s[8][132];
    const int yy = blockIdx.x;
    const int g  = blockIdx.y;
    const int b  = blockIdx.z;
    const int tid = threadIdx.x;

    const size_t rbase = ((size_t)(b * CIN + g * CPGn)) * HWi + (size_t)yy * Wn;
    for (int e = tid; e < 8 * Wn; e += 256) {
        int c = e / Wn, xx = e - c * Wn;
        s[c][xx] = x[rbase + (size_t)c * HWi + xx];
    }
    __syncthreads();

    const size_t wbase = (((size_t)(b * Gn + g)) * HWi + (size_t)yy * Wn) * CPGn;
    for (int e = tid; e < 8 * Wn; e += 256) {
        int xx = e >> 3, c = e & 7;
        g_xt[wbase + e] = s[c][xx];
    }
}

// ---------------------------------------------------------------------------
// Kernel 1: 3x3 VALID conv, 64->64. Reg-neutral FFMA2 (round-9, 516us).
// ---------------------------------------------------------------------------
__global__ __launch_bounds__(256, 4) void conv3x3_kernel(
    const float* __restrict__ x, const float* __restrict__ w1,
    const float* __restrict__ b1)
{
    const int tx = threadIdx.x;
    const int ty = threadIdx.y;
    const int tid = ty * 32 + tx;
    const int tileX = blockIdx.x * 32;
    const int tileY = blockIdx.y * 16;
    const int b = blockIdx.z >> 2;
    const int coBase = (blockIdx.z & 3) * 16;

    __shared__ float s_in[2][18][36];
    __shared__ __align__(16) float s_w[2][9][16];

    unsigned long long acc0[8], acc1[8];
#pragma unroll
    for (int i = 0; i < 8; ++i) { acc0[i] = 0ull; acc1[i] = 0ull; }

    for (int ci0 = 0; ci0 < CIN; ci0 += 2) {
#pragma unroll
        for (int cc = 0; cc < 2; ++cc) {
            const float* xp = x + ((size_t)(b * CIN + ci0 + cc)) * HWi;
            for (int e = tid; e < 18 * 34; e += 256) {
                int r = e / 34, c = e - r * 34;
                s_in[cc][r][c] = xp[(tileY + r) * Wn + (tileX + c)];
            }
        }
        for (int e = tid; e < 288; e += 256) {
            int cc = e / 144;
            int k  = (e % 144) >> 4;
            int co = e & 15;
            s_w[cc][k][co] = w1[((size_t)(coBase + co) * CIN + ci0 + cc) * 9 + k];
        }
        __syncthreads();

#pragma unroll
        for (int cc = 0; cc < 2; ++cc) {
            float in[4][3];
#pragma unroll
            for (int r = 0; r < 4; ++r)
#pragma unroll
                for (int c = 0; c < 3; ++c)
                    in[r][c] = s_in[cc][ty * 2 + r][tx + c];

#pragma unroll
            for (int ky = 0; ky < 3; ++ky)
#pragma unroll
                for (int kx = 0; kx < 3; ++kx) {
                    unsigned long long i0 = pack2(in[ky][kx]);
                    unsigned long long i1 = pack2(in[ky + 1][kx]);
                    const ulonglong2* wp = (const ulonglong2*)s_w[cc][ky * 3 + kx];
#pragma unroll
                    for (int q = 0; q < 4; ++q) {
                        ulonglong2 w = wp[q];
                        ffma2(acc0[q * 2 + 0], w.x, i0);
                        ffma2(acc0[q * 2 + 1], w.y, i0);
                        ffma2(acc1[q * 2 + 0], w.x, i1);
                        ffma2(acc1[q * 2 + 1], w.y, i1);
                    }
                }
        }
        __syncthreads();
    }

    const int oy = tileY + ty * 2;
    const int ox = tileX + tx;
#pragma unroll
    for (int q = 0; q < 8; ++q) {
        float a0lo, a0hi, a1lo, a1hi;
        unpack2(acc0[q], a0lo, a0hi);
        unpack2(acc1[q], a1lo, a1hi);
        int co = coBase + q * 2;
        float bb0 = b1[co], bb1 = b1[co + 1];
        size_t base0 = ((size_t)(b * COUT + co)) * HWo;
        size_t base1 = base0 + HWo;
        g_t[base0 + (size_t)oy * WOn + ox]       = a0lo + bb0;
        g_t[base0 + (size_t)(oy + 1) * WOn + ox] = a1lo + bb0;
        g_t[base1 + (size_t)oy * WOn + ox]       = a0hi + bb1;
        g_t[base1 + (size_t)(oy + 1) * WOn + ox] = a1hi + bb1;
    }
}

// ---------------------------------------------------------------------------
// Kernel 2: 1x1 conv 64->144 (offset prediction), FFMA2 packed (reg-neutral).
// ---------------------------------------------------------------------------
__global__ __launch_bounds__(256, 2) void conv1x1_kernel(
    const float* __restrict__ w2, const float* __restrict__ b2,
    float* __restrict__ off)
{
    __shared__ __align__(16) float s_w[64 * 48];
    __shared__ float s_t[16][256];

    const int tid = threadIdx.x;
    const int coBase = blockIdx.y * 48;
    const int p0 = blockIdx.x * 256;
    const int b = p0 >> 14;
    const int hwBase = p0 & (HWo - 1);

    for (int e = tid; e < 64 * 48; e += 256) {
        int cin = e / 48, co = e - cin * 48;
        s_w[e] = w2[(size_t)(coBase + co) * CIN + cin];
    }

    unsigned long long acc[24];
#pragma unroll
    for (int i = 0; i < 24; ++i) acc[i] = 0ull;

    for (int chunk = 0; chunk < 4; ++chunk) {
        __syncthreads();
#pragma unroll
        for (int r = 0; r < 16; ++r)
            s_t[r][tid] = g_t[((size_t)(b * CIN + chunk * 16 + r)) * HWo + hwBase + tid];
        __syncthreads();
#pragma unroll
        for (int r = 0; r < 16; ++r) {
            unsigned long long tv = pack2(s_t[r][tid]);
            const ulonglong2* wp = (const ulonglong2*)(s_w + (chunk * 16 + r) * 48);
#pragma unroll
            for (int q = 0; q < 12; ++q) {
                ulonglong2 w = wp[q];
                ffma2(acc[q * 2 + 0], w.x, tv);
                ffma2(acc[q * 2 + 1], w.y, tv);
            }
        }
    }

    const int hw = hwBase + tid;
#pragma unroll
    for (int q = 0; q < 24; ++q) {
        float lo, hi;
        unpack2(acc[q], lo, hi);
        int co = coBase + q * 2;
        off[((size_t)(b * OFFC + co)) * HWo + hw]     = lo + b2[co];
        off[((size_t)(b * OFFC + co + 1)) * HWo + hw] = hi + b2[co + 1];
    }
}

// ---------------------------------------------------------------------------
// Kernel 3: deformable conv, two-phase per tap.
// Phase A: thread = 1 px -> bilinear v[8c] -> s_v[c][256px].
// Phase B: thread = 8co x 8px (px-packed FFMA2), weights from smem
//          pre-duplicated u64 (read once per 8 px instead of per px).
// ---------------------------------------------------------------------------
__global__ __launch_bounds__(256, 2) void deform_kernel(
    const float* __restrict__ wd, const float* __restrict__ off,
    float* __restrict__ y)
{
    __shared__ __align__(16) unsigned long long s_wd2[9 * 8 * 64]; // 36864 B [ij][c][co] dup-pairs
    __shared__ __align__(16) float s_v[8][256];                    //  8192 B [c][px]

    const int tid  = threadIdx.x;          // 0..255
    const int lane = tid & 31;
    const int hoBase = blockIdx.y * 8;
    const int woBase = blockIdx.x * 32;
    const int ho = hoBase + (tid >> 5);
    const int wo = woBase + lane;
    const int b  = blockIdx.z;

    const int cog = (tid >> 5) * 8;        // phase-B co group (warp-uniform)
    const int l4  = lane * 4;              // phase-B px chunk base

    unsigned long long acc[8][4];
#pragma unroll
    for (int i = 0; i < 8; ++i)
#pragma unroll
        for (int k = 0; k < 4; ++k) acc[i][k] = 0ull;

    for (int g = 0; g < Gn; ++g) {
        // stage dup-pair weights for this group (prev phase-B reads were
        // fenced by the trailing barrier of the previous tap)
        for (int e = tid; e < 4608; e += 256) {
            int co = e & 63;
            int c  = (e >> 6) & 7;
            int ij = e >> 9;
            int i = ij / 3, j = ij - i * 3;
            float w = wd[(((size_t)co * CIN + g * CPGn + c) * 3 + i) * 3 + j];
            s_wd2[(ij * 8 + c) * 64 + co] = pack2(w);
        }
        // sync so tap-0 phase B sees the staged weights
        __syncthreads();

        const float* xg = g_xt + ((size_t)(b * Gn + g)) * HWi * CPGn;

        for (int ij = 0; ij < 9; ++ij) {
            const int i = ij / 3, j = ij - i * 3;

            // ---------------- Phase A: gather ----------------
            {
                const size_t obase = ((size_t)(b * OFFC + (g * 9 + ij) * 2)) * HWo
                                   + ho * WOn + wo;
                float dy = __ldg(off + obase);
                float dx = __ldg(off + obase + HWo);

                float py = dy + (float)(ho + i);
                float px = dx + (float)(wo + j);
                float y0f = floorf(py), x0f = floorf(px);
                float ly = py - y0f, lx = px - x0f;
                int y0 = (int)y0f, x0 = (int)x0f;
                int y1 = y0 + 1, x1 = x0 + 1;

                float vy0 = (y0 >= 0 && y0 < Hn) ? 1.f : 0.f;
                float vy1 = (y1 >= 0 && y1 < Hn) ? 1.f : 0.f;
                float vx0 = (x0 >= 0 && x0 < Wn) ? 1.f : 0.f;
                float vx1 = (x1 >= 0 && x1 < Wn) ? 1.f : 0.f;

                float w00 = (1.f - ly) * (1.f - lx) * vy0 * vx0;
                float w01 = (1.f - ly) * lx * vy0 * vx1;
                float w10 = ly * (1.f - lx) * vy1 * vx0;
                float w11 = ly * lx * vy1 * vx1;

                int yc0 = min(max(y0, 0), Hn - 1), yc1 = min(max(y1, 0), Hn - 1);
                int xc0 = min(max(x0, 0), Wn - 1), xc1 = min(max(x1, 0), Wn - 1);
                const float4* p00 = (const float4*)(xg + (size_t)(yc0 * Wn + xc0) * 8);
                const float4* p01 = (const float4*)(xg + (size_t)(yc0 * Wn + xc1) * 8);
                const float4* p10 = (const float4*)(xg + (size_t)(yc1 * Wn + xc0) * 8);
                const float4* p11 = (const float4*)(xg + (size_t)(yc1 * Wn + xc1) * 8);

                float4 a00 = __ldg(p00), b00 = __ldg(p00 + 1);
                float4 a01 = __ldg(p01), b01 = __ldg(p01 + 1);
                float4 a10 = __ldg(p10), b10 = __ldg(p10 + 1);
                float4 a11 = __ldg(p11), b11 = __ldg(p11 + 1);

                s_v[0][tid] = w00 * a00.x + w01 * a01.x + w10 * a10.x + w11 * a11.x;
                s_v[1][tid] = w00 * a00.y + w01 * a01.y + w10 * a10.y + w11 * a11.y;
                s_v[2][tid] = w00 * a00.z + w01 * a01.z + w10 * a10.z + w11 * a11.z;
                s_v[3][tid] = w00 * a00.w + w01 * a01.w + w10 * a10.w + w11 * a11.w;
                s_v[4][tid] = w00 * b00.x + w01 * b01.x + w10 * b10.x + w11 * b11.x;
                s_v[5][tid] = w00 * b00.y + w01 * b01.y + w10 * b10.y + w11 * b11.y;
                s_v[6][tid] = w00 * b00.z + w01 * b01.z + w10 * b10.z + w11 * b11.z;
                s_v[7][tid] = w00 * b00.w + w01 * b01.w + w10 * b10.w + w11 * b11.w;
            }
            __syncthreads();

            // ---------------- Phase B: register-tiled accumulate ----------
            {
                const unsigned long long* wij = s_wd2 + ij * 512;
#pragma unroll
                for (int c = 0; c < 8; ++c) {
                    ulonglong2 va = *(const ulonglong2*)&s_v[c][l4];
                    ulonglong2 vb = *(const ulonglong2*)&s_v[c][128 + l4];
                    const ulonglong2* wrow = (const ulonglong2*)(wij + c * 64 + cog);
#pragma unroll
                    for (int q = 0; q < 4; ++q) {
                        ulonglong2 w = wrow[q];
                        ffma2(acc[q * 2 + 0][0], w.x, va.x);
                        ffma2(acc[q * 2 + 0][1], w.x, va.y);
                        ffma2(acc[q * 2 + 0][2], w.x, vb.x);
                        ffma2(acc[q * 2 + 0][3], w.x, vb.y);
                        ffma2(acc[q * 2 + 1][0], w.y, va.x);
                        ffma2(acc[q * 2 + 1][1], w.y, va.y);
                        ffma2(acc[q * 2 + 1][2], w.y, vb.x);
                        ffma2(acc[q * 2 + 1][3], w.y, vb.y);
                    }
                }
            }
            __syncthreads();   // s_v (and last tap: s_wd2) safe to overwrite
        }
    }

    // Write out: thread owns co [cog, cog+8) x px chunks {l4..l4+3, 128+l4..}
#pragma unroll
    for (int col = 0; col < 8; ++col) {
        const int co = cog + col;
        const size_t cb = ((size_t)(b * COUT + co)) * HWo;
#pragma unroll
        for (int k = 0; k < 2; ++k) {
            const int p = l4 + k * 128;
            const int r = p >> 5, cc = p & 31;
            float f0, f1, f2, f3;
            unpack2(acc[col][2 * k + 0], f0, f1);
            unpack2(acc[col][2 * k + 1], f2, f3);
            *(float4*)&y[cb + (size_t)(hoBase + r) * WOn + (woBase + cc)] =
                make_float4(f0, f1, f2, f3);
        }
    }
}

// ---------------------------------------------------------------------------
extern "C" void kernel_launch(void* const* d_in, const int* in_sizes, int n_in,
                              void* d_out, int out_size)
{
    const float* x  = (const float*)d_in[0];
    const float* w1 = (const float*)d_in[1];
    const float* b1 = (const float*)d_in[2];
    const float* w2 = (const float*)d_in[3];
    const float* b2 = (const float*)d_in[4];
    const float* wd = (const float*)d_in[5];

    float* y   = (float*)d_out;
    float* off = y + (size_t)Bn * COUT * HOn * WOn;   // off is output #2

    transpose_kernel<<<dim3(Hn, Gn, Bn), 256>>>(x);
    conv3x3_kernel<<<dim3(4, 8, Bn * 4), dim3(32, 8)>>>(x, w1, b1);
    conv1x1_kernel<<<dim3((Bn * HWo) / 256, 3), 256>>>(w2, b2, off);
    deform_kernel<<<dim3(WOn / 32, HOn / 8, Bn), 256>>>(wd, off, y);
}

// round 15
// speedup vs baseline: 1.1625x; 1.0562x over previous
#include <cuda_runtime.h>

#define Bn   16
#define CIN  64
#define COUT 64
#define Hn   130
#define Wn   130
#define HOn  128
#define WOn  128
#define Gn   8
#define CPGn 8
#define OFFC 144   // G*2*K*K
#define HWo  16384 // 128*128
#define HWi  16900 // 130*130

// Intermediate feature map t = conv3x3(x, w1) + b1  : [16,64,128,128]
__device__ float g_t[(size_t)Bn * CIN * HOn * WOn];
// Transposed input: xt[b][g][y][x][c8] (grouped NHWC8)
__device__ float g_xt[(size_t)Bn * Gn * HWi * CPGn];

// ---- packed fp32x2 helpers (Blackwell FFMA2, PTX-only) ---------------------
__device__ __forceinline__ unsigned long long pack2(float v) {
    unsigned long long r;
    asm("mov.b64 %0, {%1, %1};" : "=l"(r) : "f"(v));
    return r;
}
__device__ __forceinline__ void ffma2(unsigned long long& a,
                                      unsigned long long w,
                                      unsigned long long v) {
    asm("fma.rn.f32x2 %0, %1, %2, %0;" : "+l"(a) : "l"(w), "l"(v));
}
__device__ __forceinline__ void unpack2(unsigned long long a, float& lo, float& hi) {
    asm("mov.b64 {%0, %1}, %2;" : "=f"(lo), "=f"(hi) : "l"(a));
}

// ---------------------------------------------------------------------------
// Kernel 0: transpose x [b, g*8+c, y, x] -> xt [b, g, y, x, c8].
// ---------------------------------------------------------------------------
__global__ __launch_bounds__(256) void transpose_kernel(const float* __restrict__ x)
{
    __shared__ float s[8][132];
    const int yy = blockIdx.x;
    const int g  = blockIdx.y;
    const int b  = blockIdx.z;
    const int tid = threadIdx.x;

    const size_t rbase = ((size_t)(b * CIN + g * CPGn)) * HWi + (size_t)yy * Wn;
    for (int e = tid; e < 8 * Wn; e += 256) {
        int c = e / Wn, xx = e - c * Wn;
        s[c][xx] = x[rbase + (size_t)c * HWi + xx];
    }
    __syncthreads();

    const size_t wbase = (((size_t)(b * Gn + g)) * HWi + (size_t)yy * Wn) * CPGn;
    for (int e = tid; e < 8 * Wn; e += 256) {
        int xx = e >> 3, c = e & 7;
        g_xt[wbase + e] = s[c][xx];
    }
}

// ---------------------------------------------------------------------------
// Kernel 1: 3x3 VALID conv, 64->64. Reg-neutral FFMA2 (round-9, 516us).
// ---------------------------------------------------------------------------
__global__ __launch_bounds__(256, 4) void conv3x3_kernel(
    const float* __restrict__ x, const float* __restrict__ w1,
    const float* __restrict__ b1)
{
    const int tx = threadIdx.x;
    const int ty = threadIdx.y;
    const int tid = ty * 32 + tx;
    const int tileX = blockIdx.x * 32;
    const int tileY = blockIdx.y * 16;
    const int b = blockIdx.z >> 2;
    const int coBase = (blockIdx.z & 3) * 16;

    __shared__ float s_in[2][18][36];
    __shared__ __align__(16) float s_w[2][9][16];

    unsigned long long acc0[8], acc1[8];
#pragma unroll
    for (int i = 0; i < 8; ++i) { acc0[i] = 0ull; acc1[i] = 0ull; }

    for (int ci0 = 0; ci0 < CIN; ci0 += 2) {
#pragma unroll
        for (int cc = 0; cc < 2; ++cc) {
            const float* xp = x + ((size_t)(b * CIN + ci0 + cc)) * HWi;
            for (int e = tid; e < 18 * 34; e += 256) {
                int r = e / 34, c = e - r * 34;
                s_in[cc][r][c] = xp[(tileY + r) * Wn + (tileX + c)];
            }
        }
        for (int e = tid; e < 288; e += 256) {
            int cc = e / 144;
            int k  = (e % 144) >> 4;
            int co = e & 15;
            s_w[cc][k][co] = w1[((size_t)(coBase + co) * CIN + ci0 + cc) * 9 + k];
        }
        __syncthreads();

#pragma unroll
        for (int cc = 0; cc < 2; ++cc) {
            float in[4][3];
#pragma unroll
            for (int r = 0; r < 4; ++r)
#pragma unroll
                for (int c = 0; c < 3; ++c)
                    in[r][c] = s_in[cc][ty * 2 + r][tx + c];

#pragma unroll
            for (int ky = 0; ky < 3; ++ky)
#pragma unroll
                for (int kx = 0; kx < 3; ++kx) {
                    unsigned long long i0 = pack2(in[ky][kx]);
                    unsigned long long i1 = pack2(in[ky + 1][kx]);
                    const ulonglong2* wp = (const ulonglong2*)s_w[cc][ky * 3 + kx];
#pragma unroll
                    for (int q = 0; q < 4; ++q) {
                        ulonglong2 w = wp[q];
                        ffma2(acc0[q * 2 + 0], w.x, i0);
                        ffma2(acc0[q * 2 + 1], w.y, i0);
                        ffma2(acc1[q * 2 + 0], w.x, i1);
                        ffma2(acc1[q * 2 + 1], w.y, i1);
                    }
                }
        }
        __syncthreads();
    }

    const int oy = tileY + ty * 2;
    const int ox = tileX + tx;
#pragma unroll
    for (int q = 0; q < 8; ++q) {
        float a0lo, a0hi, a1lo, a1hi;
        unpack2(acc0[q], a0lo, a0hi);
        unpack2(acc1[q], a1lo, a1hi);
        int co = coBase + q * 2;
        float bb0 = b1[co], bb1 = b1[co + 1];
        size_t base0 = ((size_t)(b * COUT + co)) * HWo;
        size_t base1 = base0 + HWo;
        g_t[base0 + (size_t)oy * WOn + ox]       = a0lo + bb0;
        g_t[base0 + (size_t)(oy + 1) * WOn + ox] = a1lo + bb0;
        g_t[base1 + (size_t)oy * WOn + ox]       = a0hi + bb1;
        g_t[base1 + (size_t)(oy + 1) * WOn + ox] = a1hi + bb1;
    }
}

// ---------------------------------------------------------------------------
// Kernel 2: 1x1 conv 64->144 (offset prediction), FFMA2 packed (reg-neutral).
// ---------------------------------------------------------------------------
__global__ __launch_bounds__(256, 2) void conv1x1_kernel(
    const float* __restrict__ w2, const float* __restrict__ b2,
    float* __restrict__ off)
{
    __shared__ __align__(16) float s_w[64 * 48];
    __shared__ float s_t[16][256];

    const int tid = threadIdx.x;
    const int coBase = blockIdx.y * 48;
    const int p0 = blockIdx.x * 256;
    const int b = p0 >> 14;
    const int hwBase = p0 & (HWo - 1);

    for (int e = tid; e < 64 * 48; e += 256) {
        int cin = e / 48, co = e - cin * 48;
        s_w[e] = w2[(size_t)(coBase + co) * CIN + cin];
    }

    unsigned long long acc[24];
#pragma unroll
    for (int i = 0; i < 24; ++i) acc[i] = 0ull;

    for (int chunk = 0; chunk < 4; ++chunk) {
        __syncthreads();
#pragma unroll
        for (int r = 0; r < 16; ++r)
            s_t[r][tid] = g_t[((size_t)(b * CIN + chunk * 16 + r)) * HWo + hwBase + tid];
        __syncthreads();
#pragma unroll
        for (int r = 0; r < 16; ++r) {
            unsigned long long tv = pack2(s_t[r][tid]);
            const ulonglong2* wp = (const ulonglong2*)(s_w + (chunk * 16 + r) * 48);
#pragma unroll
            for (int q = 0; q < 12; ++q) {
                ulonglong2 w = wp[q];
                ffma2(acc[q * 2 + 0], w.x, tv);
                ffma2(acc[q * 2 + 1], w.y, tv);
            }
        }
    }

    const int hw = hwBase + tid;
#pragma unroll
    for (int q = 0; q < 24; ++q) {
        float lo, hi;
        unpack2(acc[q], lo, hi);
        int co = coBase + q * 2;
        off[((size_t)(b * OFFC + co)) * HWo + hw]     = lo + b2[co];
        off[((size_t)(b * OFFC + co + 1)) * HWo + hw] = hi + b2[co + 1];
    }
}

// ---------------------------------------------------------------------------
// Kernel 3: deformable conv, two-phase per tap with 2D warp tiling.
// Phase A: thread = 1 px -> bilinear v[8c] -> s_v[c][256px].
// Phase B: warp grid 4(px-quadrant) x 2(co-half); thread = 16 co x 4 px.
//          v is the packed-dup operand (pack2 from one LDS.128); weights are
//          natural co-pair u64 reads from plain-float smem.
//          Each warp reads only its 64-px / 32-co slices (no cross-warp dup).
// ---------------------------------------------------------------------------
__global__ __launch_bounds__(256, 2) void deform_kernel(
    const float* __restrict__ wd, const float* __restrict__ off,
    float* __restrict__ y)
{
    __shared__ __align__(16) float s_w[9 * 8 * 64];   // 18432 B [ij][c][co] plain float
    __shared__ __align__(16) float s_v[8][256];       //  8192 B [c][px]

    const int tid  = threadIdx.x;          // 0..255
    const int lane = tid & 31;
    const int wid  = tid >> 5;             // 0..7
    const int hoBase = blockIdx.y * 8;
    const int woBase = blockIdx.x * 32;
    const int ho = hoBase + wid;           // phase-A row
    const int wo = woBase + lane;          // phase-A col
    const int b  = blockIdx.z;

    // Phase-B tile coordinates
    const int wp = wid & 3;                          // px quadrant (64 px)
    const int wc = wid >> 2;                         // co half (32 co)
    const int coStart = wc * 32 + (lane >> 4) * 16;  // 16 co per thread
    const int pxBase  = wp * 64 + (lane & 15) * 4;   // 4 px per thread

    unsigned long long acc[8][4];   // [co-pair][px] ; u64 lanes = (co2p, co2p+1)
#pragma unroll
    for (int i = 0; i < 8; ++i)
#pragma unroll
        for (int k = 0; k < 4; ++k) acc[i][k] = 0ull;

    for (int g = 0; g < Gn; ++g) {
        // stage plain-float weights for this group (prev reads fenced by the
        // trailing barrier of the previous tap)
        for (int e = tid; e < 4608; e += 256) {
            int co = e & 63;
            int c  = (e >> 6) & 7;
            int ij = e >> 9;
            int i = ij / 3, j = ij - i * 3;
            s_w[e] = wd[(((size_t)co * CIN + g * CPGn + c) * 3 + i) * 3 + j];
        }
        __syncthreads();   // weights visible to tap-0 phase B

        const float* xg = g_xt + ((size_t)(b * Gn + g)) * HWi * CPGn;

        for (int ij = 0; ij < 9; ++ij) {
            const int i = ij / 3, j = ij - i * 3;

            // ---------------- Phase A: gather ----------------
            {
                const size_t obase = ((size_t)(b * OFFC + (g * 9 + ij) * 2)) * HWo
                                   + ho * WOn + wo;
                float dy = __ldg(off + obase);
                float dx = __ldg(off + obase + HWo);

                float py = dy + (float)(ho + i);
                float px = dx + (float)(wo + j);
                float y0f = floorf(py), x0f = floorf(px);
                float ly = py - y0f, lx = px - x0f;
                int y0 = (int)y0f, x0 = (int)x0f;
                int y1 = y0 + 1, x1 = x0 + 1;

                float vy0 = (y0 >= 0 && y0 < Hn) ? 1.f : 0.f;
                float vy1 = (y1 >= 0 && y1 < Hn) ? 1.f : 0.f;
                float vx0 = (x0 >= 0 && x0 < Wn) ? 1.f : 0.f;
                float vx1 = (x1 >= 0 && x1 < Wn) ? 1.f : 0.f;

                float w00 = (1.f - ly) * (1.f - lx) * vy0 * vx0;
                float w01 = (1.f - ly) * lx * vy0 * vx1;
                float w10 = ly * (1.f - lx) * vy1 * vx0;
                float w11 = ly * lx * vy1 * vx1;

                int yc0 = min(max(y0, 0), Hn - 1), yc1 = min(max(y1, 0), Hn - 1);
                int xc0 = min(max(x0, 0), Wn - 1), xc1 = min(max(x1, 0), Wn - 1);
                const float4* p00 = (const float4*)(xg + (size_t)(yc0 * Wn + xc0) * 8);
                const float4* p01 = (const float4*)(xg + (size_t)(yc0 * Wn + xc1) * 8);
                const float4* p10 = (const float4*)(xg + (size_t)(yc1 * Wn + xc0) * 8);
                const float4* p11 = (const float4*)(xg + (size_t)(yc1 * Wn + xc1) * 8);

                float4 a00 = __ldg(p00), b00 = __ldg(p00 + 1);
                float4 a01 = __ldg(p01), b01 = __ldg(p01 + 1);
                float4 a10 = __ldg(p10), b10 = __ldg(p10 + 1);
                float4 a11 = __ldg(p11), b11 = __ldg(p11 + 1);

                s_v[0][tid] = w00 * a00.x + w01 * a01.x + w10 * a10.x + w11 * a11.x;
                s_v[1][tid] = w00 * a00.y + w01 * a01.y + w10 * a10.y + w11 * a11.y;
                s_v[2][tid] = w00 * a00.z + w01 * a01.z + w10 * a10.z + w11 * a11.z;
                s_v[3][tid] = w00 * a00.w + w01 * a01.w + w10 * a10.w + w11 * a11.w;
                s_v[4][tid] = w00 * b00.x + w01 * b01.x + w10 * b10.x + w11 * b11.x;
                s_v[5][tid] = w00 * b00.y + w01 * b01.y + w10 * b10.y + w11 * b11.y;
                s_v[6][tid] = w00 * b00.z + w01 * b01.z + w10 * b10.z + w11 * b11.z;
                s_v[7][tid] = w00 * b00.w + w01 * b01.w + w10 * b10.w + w11 * b11.w;
            }
            __syncthreads();

            // ---------------- Phase B: 2D warp-tiled accumulate ----------
            {
                const float* wij = s_w + ij * 512;   // [c][64]
#pragma unroll
                for (int c = 0; c < 8; ++c) {
                    float4 vf = *(const float4*)&s_v[c][pxBase];
                    unsigned long long v0 = pack2(vf.x);
                    unsigned long long v1 = pack2(vf.y);
                    unsigned long long v2 = pack2(vf.z);
                    unsigned long long v3 = pack2(vf.w);

                    const ulonglong2* wrow = (const ulonglong2*)(wij + c * 64 + coStart);
                    ulonglong2 wA = wrow[0];   // co pairs (0,1),(2,3)
                    ulonglong2 wB = wrow[1];   // (4,5),(6,7)
                    ulonglong2 wC = wrow[2];   // (8,9),(10,11)
                    ulonglong2 wD = wrow[3];   // (12,13),(14,15)

                    ffma2(acc[0][0], wA.x, v0); ffma2(acc[0][1], wA.x, v1);
                    ffma2(acc[0][2], wA.x, v2); ffma2(acc[0][3], wA.x, v3);
                    ffma2(acc[1][0], wA.y, v0); ffma2(acc[1][1], wA.y, v1);
                    ffma2(acc[1][2], wA.y, v2); ffma2(acc[1][3], wA.y, v3);
                    ffma2(acc[2][0], wB.x, v0); ffma2(acc[2][1], wB.x, v1);
                    ffma2(acc[2][2], wB.x, v2); ffma2(acc[2][3], wB.x, v3);
                    ffma2(acc[3][0], wB.y, v0); ffma2(acc[3][1], wB.y, v1);
                    ffma2(acc[3][2], wB.y, v2); ffma2(acc[3][3], wB.y, v3);
                    ffma2(acc[4][0], wC.x, v0); ffma2(acc[4][1], wC.x, v1);
                    ffma2(acc[4][2], wC.x, v2); ffma2(acc[4][3], wC.x, v3);
                    ffma2(acc[5][0], wC.y, v0); ffma2(acc[5][1], wC.y, v1);
                    ffma2(acc[5][2], wC.y, v2); ffma2(acc[5][3], wC.y, v3);
                    ffma2(acc[6][0], wD.x, v0); ffma2(acc[6][1], wD.x, v1);
                    ffma2(acc[6][2], wD.x, v2); ffma2(acc[6][3], wD.x, v3);
                    ffma2(acc[7][0], wD.y, v0); ffma2(acc[7][1], wD.y, v1);
                    ffma2(acc[7][2], wD.y, v2); ffma2(acc[7][3], wD.y, v3);
                }
            }
            __syncthreads();   // s_v (and last tap: s_w) safe to overwrite
        }
    }

    // Writeout: thread owns co [coStart, coStart+16) x px [pxBase, pxBase+4).
    const int r  = pxBase >> 5;
    const int cc = pxBase & 31;
    const size_t rowOff = (size_t)(hoBase + r) * WOn + (woBase + cc);
#pragma unroll
    for (int p = 0; p < 8; ++p) {
        float lo0, hi0, lo1, hi1, lo2, hi2, lo3, hi3;
        unpack2(acc[p][0], lo0, hi0);
        unpack2(acc[p][1], lo1, hi1);
        unpack2(acc[p][2], lo2, hi2);
        unpack2(acc[p][3], lo3, hi3);
        const int co = coStart + p * 2;
        *(float4*)&y[((size_t)(b * COUT + co)) * HWo + rowOff] =
            make_float4(lo0, lo1, lo2, lo3);
        *(float4*)&y[((size_t)(b * COUT + co + 1)) * HWo + rowOff] =
            make_float4(hi0, hi1, hi2, hi3);
    }
}

// ---------------------------------------------------------------------------
extern "C" void kernel_launch(void* const* d_in, const int* in_sizes, int n_in,
                              void* d_out, int out_size)
{
    const float* x  = (const float*)d_in[0];
    const float* w1 = (const float*)d_in[1];
    const float* b1 = (const float*)d_in[2];
    const float* w2 = (const float*)d_in[3];
    const float* b2 = (const float*)d_in[4];
    const float* wd = (const float*)d_in[5];

    float* y   = (float*)d_out;
    float* off = y + (size_t)Bn * COUT * HOn * WOn;   // off is output #2

    transpose_kernel<<<dim3(Hn, Gn, Bn), 256>>>(x);
    conv3x3_kernel<<<dim3(4, 8, Bn * 4), dim3(32, 8)>>>(x, w1, b1);
    conv1x1_kernel<<<dim3((Bn * HWo) / 256, 3), 256>>>(w2, b2, off);
    deform_kernel<<<dim3(WOn / 32, HOn / 8, Bn), 256>>>(wd, off, y);
}

// round 16
// speedup vs baseline: 1.1914x; 1.0249x over previous
#include <cuda_runtime.h>

#define Bn   16
#define CIN  64
#define COUT 64
#define Hn   130
#define Wn   130
#define HOn  128
#define WOn  128
#define Gn   8
#define CPGn 8
#define OFFC 144   // G*2*K*K
#define HWo  16384 // 128*128
#define HWi  16900 // 130*130

// Intermediate feature map t = conv3x3(x, w1) + b1  : [16,64,128,128]
__device__ float g_t[(size_t)Bn * CIN * HOn * WOn];
// Transposed input: xt[b][g][y][x][c8] (grouped NHWC8)
__device__ float g_xt[(size_t)Bn * Gn * HWi * CPGn];

// ---- packed fp32x2 helpers (Blackwell FFMA2, PTX-only) ---------------------
__device__ __forceinline__ unsigned long long pack2(float v) {
    unsigned long long r;
    asm("mov.b64 %0, {%1, %1};" : "=l"(r) : "f"(v));
    return r;
}
__device__ __forceinline__ void ffma2(unsigned long long& a,
                                      unsigned long long w,
                                      unsigned long long v) {
    asm("fma.rn.f32x2 %0, %1, %2, %0;" : "+l"(a) : "l"(w), "l"(v));
}
__device__ __forceinline__ void unpack2(unsigned long long a, float& lo, float& hi) {
    asm("mov.b64 {%0, %1}, %2;" : "=f"(lo), "=f"(hi) : "l"(a));
}

// ---------------------------------------------------------------------------
// Kernel 0: transpose x [b, g*8+c, y, x] -> xt [b, g, y, x, c8].
// ---------------------------------------------------------------------------
__global__ __launch_bounds__(256) void transpose_kernel(const float* __restrict__ x)
{
    __shared__ float s[8][132];
    const int yy = blockIdx.x;
    const int g  = blockIdx.y;
    const int b  = blockIdx.z;
    const int tid = threadIdx.x;

    const size_t rbase = ((size_t)(b * CIN + g * CPGn)) * HWi + (size_t)yy * Wn;
    for (int e = tid; e < 8 * Wn; e += 256) {
        int c = e / Wn, xx = e - c * Wn;
        s[c][xx] = x[rbase + (size_t)c * HWi + xx];
    }
    __syncthreads();

    const size_t wbase = (((size_t)(b * Gn + g)) * HWi + (size_t)yy * Wn) * CPGn;
    for (int e = tid; e < 8 * Wn; e += 256) {
        int xx = e >> 3, c = e & 7;
        g_xt[wbase + e] = s[c][xx];
    }
}

// ---------------------------------------------------------------------------
// Kernel 1: 3x3 VALID conv, 64->64. Reg-neutral FFMA2 (round-9, 516us).
// ---------------------------------------------------------------------------
__global__ __launch_bounds__(256, 4) void conv3x3_kernel(
    const float* __restrict__ x, const float* __restrict__ w1,
    const float* __restrict__ b1)
{
    const int tx = threadIdx.x;
    const int ty = threadIdx.y;
    const int tid = ty * 32 + tx;
    const int tileX = blockIdx.x * 32;
    const int tileY = blockIdx.y * 16;
    const int b = blockIdx.z >> 2;
    const int coBase = (blockIdx.z & 3) * 16;

    __shared__ float s_in[2][18][36];
    __shared__ __align__(16) float s_w[2][9][16];

    unsigned long long acc0[8], acc1[8];
#pragma unroll
    for (int i = 0; i < 8; ++i) { acc0[i] = 0ull; acc1[i] = 0ull; }

    for (int ci0 = 0; ci0 < CIN; ci0 += 2) {
#pragma unroll
        for (int cc = 0; cc < 2; ++cc) {
            const float* xp = x + ((size_t)(b * CIN + ci0 + cc)) * HWi;
            for (int e = tid; e < 18 * 34; e += 256) {
                int r = e / 34, c = e - r * 34;
                s_in[cc][r][c] = xp[(tileY + r) * Wn + (tileX + c)];
            }
        }
        for (int e = tid; e < 288; e += 256) {
            int cc = e / 144;
            int k  = (e % 144) >> 4;
            int co = e & 15;
            s_w[cc][k][co] = w1[((size_t)(coBase + co) * CIN + ci0 + cc) * 9 + k];
        }
        __syncthreads();

#pragma unroll
        for (int cc = 0; cc < 2; ++cc) {
            float in[4][3];
#pragma unroll
            for (int r = 0; r < 4; ++r)
#pragma unroll
                for (int c = 0; c < 3; ++c)
                    in[r][c] = s_in[cc][ty * 2 + r][tx + c];

#pragma unroll
            for (int ky = 0; ky < 3; ++ky)
#pragma unroll
                for (int kx = 0; kx < 3; ++kx) {
                    unsigned long long i0 = pack2(in[ky][kx]);
                    unsigned long long i1 = pack2(in[ky + 1][kx]);
                    const ulonglong2* wp = (const ulonglong2*)s_w[cc][ky * 3 + kx];
#pragma unroll
                    for (int q = 0; q < 4; ++q) {
                        ulonglong2 w = wp[q];
                        ffma2(acc0[q * 2 + 0], w.x, i0);
                        ffma2(acc0[q * 2 + 1], w.y, i0);
                        ffma2(acc1[q * 2 + 0], w.x, i1);
                        ffma2(acc1[q * 2 + 1], w.y, i1);
                    }
                }
        }
        __syncthreads();
    }

    const int oy = tileY + ty * 2;
    const int ox = tileX + tx;
#pragma unroll
    for (int q = 0; q < 8; ++q) {
        float a0lo, a0hi, a1lo, a1hi;
        unpack2(acc0[q], a0lo, a0hi);
        unpack2(acc1[q], a1lo, a1hi);
        int co = coBase + q * 2;
        float bb0 = b1[co], bb1 = b1[co + 1];
        size_t base0 = ((size_t)(b * COUT + co)) * HWo;
        size_t base1 = base0 + HWo;
        g_t[base0 + (size_t)oy * WOn + ox]       = a0lo + bb0;
        g_t[base0 + (size_t)(oy + 1) * WOn + ox] = a1lo + bb0;
        g_t[base1 + (size_t)oy * WOn + ox]       = a0hi + bb1;
        g_t[base1 + (size_t)(oy + 1) * WOn + ox] = a1hi + bb1;
    }
}

// ---------------------------------------------------------------------------
// Kernel 2: 1x1 conv 64->144 (offset prediction), FFMA2 packed (reg-neutral).
// ---------------------------------------------------------------------------
__global__ __launch_bounds__(256, 2) void conv1x1_kernel(
    const float* __restrict__ w2, const float* __restrict__ b2,
    float* __restrict__ off)
{
    __shared__ __align__(16) float s_w[64 * 48];
    __shared__ float s_t[16][256];

    const int tid = threadIdx.x;
    const int coBase = blockIdx.y * 48;
    const int p0 = blockIdx.x * 256;
    const int b = p0 >> 14;
    const int hwBase = p0 & (HWo - 1);

    for (int e = tid; e < 64 * 48; e += 256) {
        int cin = e / 48, co = e - cin * 48;
        s_w[e] = w2[(size_t)(coBase + co) * CIN + cin];
    }

    unsigned long long acc[24];
#pragma unroll
    for (int i = 0; i < 24; ++i) acc[i] = 0ull;

    for (int chunk = 0; chunk < 4; ++chunk) {
        __syncthreads();
#pragma unroll
        for (int r = 0; r < 16; ++r)
            s_t[r][tid] = g_t[((size_t)(b * CIN + chunk * 16 + r)) * HWo + hwBase + tid];
        __syncthreads();
#pragma unroll
        for (int r = 0; r < 16; ++r) {
            unsigned long long tv = pack2(s_t[r][tid]);
            const ulonglong2* wp = (const ulonglong2*)(s_w + (chunk * 16 + r) * 48);
#pragma unroll
            for (int q = 0; q < 12; ++q) {
                ulonglong2 w = wp[q];
                ffma2(acc[q * 2 + 0], w.x, tv);
                ffma2(acc[q * 2 + 1], w.y, tv);
            }
        }
    }

    const int hw = hwBase + tid;
#pragma unroll
    for (int q = 0; q < 24; ++q) {
        float lo, hi;
        unpack2(acc[q], lo, hi);
        int co = coBase + q * 2;
        off[((size_t)(b * OFFC + co)) * HWo + hw]     = lo + b2[co];
        off[((size_t)(b * OFFC + co + 1)) * HWo + hw] = hi + b2[co + 1];
    }
}

// ---------------------------------------------------------------------------
// Kernel 3: deformable conv, software-pipelined two-phase with ping-pong s_v.
// Per tap: ONE barrier. phaseA(ij+1) -> buf^1 issued before/interleaved with
// phaseB(ij) <- buf, so gather LDG latency is covered by FFMA2 work.
// ---------------------------------------------------------------------------
struct DeformCtx {
    const float* xg;
    const float* off;
    size_t offPixBase;   // b*OFFC plane base + ho*WOn + wo
    int ho, wo;
};

__device__ __forceinline__ void deform_phaseA(
    const DeformCtx& cx, int g, int ij, float (*sv)[256], int tid)
{
    const int i = ij / 3, j = ij - i * 3;
    const size_t obase = cx.offPixBase + (size_t)((g * 9 + ij) * 2) * HWo;
    float dy = __ldg(cx.off + obase);
    float dx = __ldg(cx.off + obase + HWo);

    float py = dy + (float)(cx.ho + i);
    float px = dx + (float)(cx.wo + j);
    float y0f = floorf(py), x0f = floorf(px);
    float ly = py - y0f, lx = px - x0f;
    int y0 = (int)y0f, x0 = (int)x0f;
    int y1 = y0 + 1, x1 = x0 + 1;

    float vy0 = (y0 >= 0 && y0 < Hn) ? 1.f : 0.f;
    float vy1 = (y1 >= 0 && y1 < Hn) ? 1.f : 0.f;
    float vx0 = (x0 >= 0 && x0 < Wn) ? 1.f : 0.f;
    float vx1 = (x1 >= 0 && x1 < Wn) ? 1.f : 0.f;

    float w00 = (1.f - ly) * (1.f - lx) * vy0 * vx0;
    float w01 = (1.f - ly) * lx * vy0 * vx1;
    float w10 = ly * (1.f - lx) * vy1 * vx0;
    float w11 = ly * lx * vy1 * vx1;

    int yc0 = min(max(y0, 0), Hn - 1), yc1 = min(max(y1, 0), Hn - 1);
    int xc0 = min(max(x0, 0), Wn - 1), xc1 = min(max(x1, 0), Wn - 1);
    const float4* p00 = (const float4*)(cx.xg + (size_t)(yc0 * Wn + xc0) * 8);
    const float4* p01 = (const float4*)(cx.xg + (size_t)(yc0 * Wn + xc1) * 8);
    const float4* p10 = (const float4*)(cx.xg + (size_t)(yc1 * Wn + xc0) * 8);
    const float4* p11 = (const float4*)(cx.xg + (size_t)(yc1 * Wn + xc1) * 8);

    // low 4 channels
    {
        float4 a00 = __ldg(p00), a01 = __ldg(p01);
        float4 a10 = __ldg(p10), a11 = __ldg(p11);
        sv[0][tid] = w00 * a00.x + w01 * a01.x + w10 * a10.x + w11 * a11.x;
        sv[1][tid] = w00 * a00.y + w01 * a01.y + w10 * a10.y + w11 * a11.y;
        sv[2][tid] = w00 * a00.z + w01 * a01.z + w10 * a10.z + w11 * a11.z;
        sv[3][tid] = w00 * a00.w + w01 * a01.w + w10 * a10.w + w11 * a11.w;
    }
    // high 4 channels
    {
        float4 b00 = __ldg(p00 + 1), b01 = __ldg(p01 + 1);
        float4 b10 = __ldg(p10 + 1), b11 = __ldg(p11 + 1);
        sv[4][tid] = w00 * b00.x + w01 * b01.x + w10 * b10.x + w11 * b11.x;
        sv[5][tid] = w00 * b00.y + w01 * b01.y + w10 * b10.y + w11 * b11.y;
        sv[6][tid] = w00 * b00.z + w01 * b01.z + w10 * b10.z + w11 * b11.z;
        sv[7][tid] = w00 * b00.w + w01 * b01.w + w10 * b10.w + w11 * b11.w;
    }
}

__global__ __launch_bounds__(256, 2) void deform_kernel(
    const float* __restrict__ wd, const float* __restrict__ off,
    float* __restrict__ y)
{
    __shared__ __align__(16) float s_w[9 * 8 * 64];     // 18432 B [ij][c][co]
    __shared__ __align__(16) float s_v[2][8][256];      // 16384 B ping-pong

    const int tid  = threadIdx.x;          // 0..255
    const int lane = tid & 31;
    const int wid  = tid >> 5;             // 0..7
    const int hoBase = blockIdx.y * 8;
    const int woBase = blockIdx.x * 32;
    const int b  = blockIdx.z;

    DeformCtx cx;
    cx.off = off;
    cx.ho = hoBase + wid;
    cx.wo = woBase + lane;
    cx.offPixBase = ((size_t)b * OFFC) * HWo + (size_t)cx.ho * WOn + cx.wo;

    // Phase-B tile coordinates
    const int wp = wid & 3;                          // px quadrant (64 px)
    const int wc = wid >> 2;                         // co half (32 co)
    const int coStart = wc * 32 + (lane >> 4) * 16;  // 16 co per thread
    const int pxBase  = wp * 64 + (lane & 15) * 4;   // 4 px per thread

    unsigned long long acc[8][4];   // [co-pair][px]
#pragma unroll
    for (int i = 0; i < 8; ++i)
#pragma unroll
        for (int k = 0; k < 4; ++k) acc[i][k] = 0ull;

    for (int g = 0; g < Gn; ++g) {
        cx.xg = g_xt + ((size_t)(b * Gn + g)) * HWi * CPGn;

        // stage weights for this group (prev-group reads fenced by the
        // trailing barrier of the last tap)
        for (int e = tid; e < 4608; e += 256) {
            int co = e & 63;
            int c  = (e >> 6) & 7;
            int ij = e >> 9;
            int i = ij / 3, j = ij - i * 3;
            s_w[e] = wd[(((size_t)co * CIN + g * CPGn + c) * 3 + i) * 3 + j];
        }
        // prologue gather: tap 0 -> buffer 0
        deform_phaseA(cx, g, 0, s_v[0], tid);
        __syncthreads();

        for (int ij = 0; ij < 9; ++ij) {
            // ---- issue next tap's gather first (LDG latency overlaps B) ----
            if (ij < 8)
                deform_phaseA(cx, g, ij + 1, s_v[(ij + 1) & 1], tid);

            // ---- Phase B: 2D warp-tiled accumulate from s_v[ij&1] ----------
            {
                const float (*svb)[256] = s_v[ij & 1];
                const float* wij = s_w + ij * 512;   // [c][64]
#pragma unroll
                for (int c = 0; c < 8; ++c) {
                    float4 vf = *(const float4*)&svb[c][pxBase];
                    unsigned long long v0 = pack2(vf.x);
                    unsigned long long v1 = pack2(vf.y);
                    unsigned long long v2 = pack2(vf.z);
                    unsigned long long v3 = pack2(vf.w);

                    const ulonglong2* wrow = (const ulonglong2*)(wij + c * 64 + coStart);
                    ulonglong2 wA = wrow[0];
                    ulonglong2 wB = wrow[1];
                    ulonglong2 wC = wrow[2];
                    ulonglong2 wD = wrow[3];

                    ffma2(acc[0][0], wA.x, v0); ffma2(acc[0][1], wA.x, v1);
                    ffma2(acc[0][2], wA.x, v2); ffma2(acc[0][3], wA.x, v3);
                    ffma2(acc[1][0], wA.y, v0); ffma2(acc[1][1], wA.y, v1);
                    ffma2(acc[1][2], wA.y, v2); ffma2(acc[1][3], wA.y, v3);
                    ffma2(acc[2][0], wB.x, v0); ffma2(acc[2][1], wB.x, v1);
                    ffma2(acc[2][2], wB.x, v2); ffma2(acc[2][3], wB.x, v3);
                    ffma2(acc[3][0], wB.y, v0); ffma2(acc[3][1], wB.y, v1);
                    ffma2(acc[3][2], wB.y, v2); ffma2(acc[3][3], wB.y, v3);
                    ffma2(acc[4][0], wC.x, v0); ffma2(acc[4][1], wC.x, v1);
                    ffma2(acc[4][2], wC.x, v2); ffma2(acc[4][3], wC.x, v3);
                    ffma2(acc[5][0], wC.y, v0); ffma2(acc[5][1], wC.y, v1);
                    ffma2(acc[5][2], wC.y, v2); ffma2(acc[5][3], wC.y, v3);
                    ffma2(acc[6][0], wD.x, v0); ffma2(acc[6][1], wD.x, v1);
                    ffma2(acc[6][2], wD.x, v2); ffma2(acc[6][3], wD.x, v3);
                    ffma2(acc[7][0], wD.y, v0); ffma2(acc[7][1], wD.y, v1);
                    ffma2(acc[7][2], wD.y, v2); ffma2(acc[7][3], wD.y, v3);
                }
            }
            // one barrier per tap: next phaseB needs this phaseA's buffer;
            // next phaseA overwrites the buffer this phaseB just read.
            __syncthreads();
        }
    }

    // Writeout: thread owns co [coStart, coStart+16) x px [pxBase, pxBase+4).
    const int r  = pxBase >> 5;
    const int cc = pxBase & 31;
    const size_t rowOff = (size_t)(hoBase + r) * WOn + (woBase + cc);
#pragma unroll
    for (int p = 0; p < 8; ++p) {
        float lo0, hi0, lo1, hi1, lo2, hi2, lo3, hi3;
        unpack2(acc[p][0], lo0, hi0);
        unpack2(acc[p][1], lo1, hi1);
        unpack2(acc[p][2], lo2, hi2);
        unpack2(acc[p][3], lo3, hi3);
        const int co = coStart + p * 2;
        *(float4*)&y[((size_t)(b * COUT + co)) * HWo + rowOff] =
            make_float4(lo0, lo1, lo2, lo3);
        *(float4*)&y[((size_t)(b * COUT + co + 1)) * HWo + rowOff] =
            make_float4(hi0, hi1, hi2, hi3);
    }
}

// ---------------------------------------------------------------------------
extern "C" void kernel_launch(void* const* d_in, const int* in_sizes, int n_in,
                              void* d_out, int out_size)
{
    const float* x  = (const float*)d_in[0];
    const float* w1 = (const float*)d_in[1];
    const float* b1 = (const float*)d_in[2];
    const float* w2 = (const float*)d_in[3];
    const float* b2 = (const float*)d_in[4];
    const float* wd = (const float*)d_in[5];

    float* y   = (float*)d_out;
    float* off = y + (size_t)Bn * COUT * HOn * WOn;   // off is output #2

    transpose_kernel<<<dim3(Hn, Gn, Bn), 256>>>(x);
    conv3x3_kernel<<<dim3(4, 8, Bn * 4), dim3(32, 8)>>>(x, w1, b1);
    conv1x1_kernel<<<dim3((Bn * HWo) / 256, 3), 256>>>(w2, b2, off);
    deform_kernel<<<dim3(WOn / 32, HOn / 8, Bn), 256>>>(wd, off, y);
}